// round 1
// baseline (speedup 1.0000x reference)
#include <cuda_runtime.h>
#include <cuda_bf16.h>
#include <math.h>

// Problem constants
#define BB 2
#define CC 64
#define HH 128
#define WW 128
#define HS 64          // downsampled H=W
#define LL 4096        // HS*HS
#define EE 1024        // CC*16 (4x4 patch)
#define LSQ (4096*4096)

// ---------------- scratch (device globals; no allocation allowed) -------------
__device__ float g_fgT[BB*CC*LL];          // [b][c][p]   2 MB
__device__ float g_bgD[BB*LL*CC];          // [b][l][c]   2 MB
__device__ float g_sq[BB*LL];
__device__ float g_ninv[BB*LL];
__device__ int   g_maskP[BB*LL];           // indexed by permuted a = j*64+i
__device__ float g_colsP[(size_t)BB*LL*EE];  // 33.5 MB, row a = j*64+i
__device__ float g_bufA[(size_t)BB*LSQ];     // 134 MB
__device__ float g_bufB[(size_t)BB*LSQ];     // 134 MB
__device__ float g_outcol[(size_t)BB*LL*EE]; // 33.5 MB, row pp = x*64+y

// ---------------- prep kernels -----------------------------------------------
__global__ void k_fgT(const float* __restrict__ fg) {
    int t = blockIdx.x * blockDim.x + threadIdx.x;
    if (t >= BB*CC*LL) return;
    int p = t & 4095, c = (t >> 12) & 63, b = t >> 18;
    int y = p >> 6, x = p & 63;
    g_fgT[((size_t)b*CC + c)*LL + p] =
        fg[(((size_t)b*CC + c)*HH + 2*y)*WW + 2*x];
}

__global__ void k_bgD(const float* __restrict__ bg) {
    int t = blockIdx.x * blockDim.x + threadIdx.x;
    if (t >= BB*LL*CC) return;
    int c = t & 63, l = (t >> 6) & 4095, b = t >> 18;
    int i = l >> 6, j = l & 63;
    g_bgD[((size_t)b*LL + l)*CC + c] =
        bg[(((size_t)b*CC + c)*HH + 2*i)*WW + 2*j];
}

// per-location sum of squares over channels (one warp per l)
__global__ void k_sq() {
    int gid = blockIdx.x * blockDim.x + threadIdx.x;
    int gw = gid >> 5;
    int lane = gid & 31;
    if (gw >= BB*LL) return;
    const float* row = g_bgD + (size_t)gw * CC;
    float v0 = row[lane], v1 = row[lane + 32];
    float s = v0*v0 + v1*v1;
    #pragma unroll
    for (int o = 16; o; o >>= 1) s += __shfl_xor_sync(0xffffffffu, s, o);
    if (lane == 0) g_sq[gw] = s;
}

// patch norms (3x3 window of sq) and mask flags (written permuted)
__global__ void k_normmask(const float* __restrict__ mask) {
    int t = blockIdx.x * blockDim.x + threadIdx.x;
    if (t >= BB*LL) return;
    int b = t >> 12, l = t & 4095;
    int i = l >> 6, j = l & 63;
    float ss = 0.f, ms = 0.f;
    for (int di = -1; di <= 1; di++) {
        int ii = i + di; if (ii < 0 || ii >= HS) continue;
        for (int dj = -1; dj <= 1; dj++) {
            int jj = j + dj; if (jj < 0 || jj >= HS) continue;
            ss += g_sq[b*LL + ii*HS + jj];
            ms += mask[((size_t)b*HH + 2*ii)*WW + 2*jj];
        }
    }
    g_ninv[t] = 1.f / fmaxf(sqrtf(ss), 1e-3f);
    g_maskP[b*LL + j*HS + i] = (ms == 0.f) ? 1 : 0;
}

// 4x4 stride-2 patches of full-res background, rows permuted: a = j*64+i
__global__ void k_cols(const float* __restrict__ bg) {
    int t = blockIdx.x * blockDim.x + threadIdx.x;
    if (t >= BB*LL*EE) return;
    int e = t & 1023;
    int a = (t >> 10) & 4095;
    // b = t >> 22 is implicit in flat layout
    int b = t >> 22;
    int j = a >> 6, i = a & 63;
    int c = e >> 4, ki = (e >> 2) & 3, kj = e & 3;
    int Y = 2*i - 1 + ki, X = 2*j - 1 + kj;
    float v = 0.f;
    if (Y >= 0 && Y < HH && X >= 0 && X < WW)
        v = bg[(((size_t)b*CC + c)*HH + Y)*WW + X];
    g_colsP[(size_t)t] = v;
}

// ---------------- GEMM1: S0[l,p] = sum_c bgD[l,c] * fgT[c,p]  -> bufA ---------
__global__ __launch_bounds__(256) void k_gemm1() {
    __shared__ float As[64][65];   // [l][c]
    __shared__ float Bs[64][65];   // [c][p]
    int b = blockIdx.z;
    int l0 = blockIdx.y * 64, p0 = blockIdx.x * 64;
    int tid = threadIdx.x;
    for (int t = tid; t < 4096; t += 256) {
        int r = t >> 6, c = t & 63;
        As[r][c] = g_bgD[((size_t)b*LL + l0 + r)*CC + c];
        Bs[r][c] = g_fgT[((size_t)b*CC + r)*LL + p0 + c];
    }
    __syncthreads();
    int tr = tid >> 4, tc = tid & 15;
    float acc[4][4];
    #pragma unroll
    for (int r = 0; r < 4; r++)
        #pragma unroll
        for (int s = 0; s < 4; s++) acc[r][s] = 0.f;
    #pragma unroll 8
    for (int k = 0; k < 64; k++) {
        float ar[4], br[4];
        #pragma unroll
        for (int r = 0; r < 4; r++) ar[r] = As[tr*4 + r][k];
        #pragma unroll
        for (int s = 0; s < 4; s++) br[s] = Bs[k][tc*4 + s];
        #pragma unroll
        for (int r = 0; r < 4; r++)
            #pragma unroll
            for (int s = 0; s < 4; s++) acc[r][s] += ar[r] * br[s];
    }
    float* D = g_bufA + (size_t)b*LSQ;
    #pragma unroll
    for (int r = 0; r < 4; r++) {
        float4 v = make_float4(acc[r][0], acc[r][1], acc[r][2], acc[r][3]);
        *(float4*)(D + (size_t)(l0 + tr*4 + r)*LL + p0 + tc*4) = v;
    }
}

// ---------------- patch-sum pass A (di over rows): bufA -> bufB ---------------
__global__ void k_diagA() {
    int t = blockIdx.x * blockDim.x + threadIdx.x;
    if (t >= BB*LL*1024) return;
    int b = t >> 22;
    int r = t & 4194303;
    int l = r >> 10;
    int p = (r & 1023) << 2;
    const float* S = g_bufA + (size_t)b*LSQ;
    float4 acc = make_float4(0.f, 0.f, 0.f, 0.f);
    #pragma unroll
    for (int di = -1; di <= 1; di++) {
        int ll = l + 64*di, pp = p + 64*di;
        if (ll >= 0 && ll < LL && pp >= 0 && pp + 3 < LL) {
            float4 v = *(const float4*)(S + (size_t)ll*LL + pp);
            acc.x += v.x; acc.y += v.y; acc.z += v.z; acc.w += v.w;
        }
    }
    *(float4*)(g_bufB + (size_t)b*LSQ + (size_t)l*LL + p) = acc;
}

// ---------------- patch-sum pass B (dj over cols) + norm: bufB -> bufA --------
__global__ void k_diagB() {
    int t = blockIdx.x * blockDim.x + threadIdx.x;
    if (t >= BB*LL*1024) return;
    int b = t >> 22;
    int r = t & 4194303;
    int l = r >> 10;
    int p = (r & 1023) << 2;
    const float* S = g_bufB + (size_t)b*LSQ;
    float* D = g_bufA + (size_t)b*LSQ;
    int j = l & 63;
    float ninv = g_ninv[b*LL + l];
    #pragma unroll
    for (int s = 0; s < 4; s++) {
        int pp = p + s;
        int x = pp & 63;
        float acc = S[(size_t)l*LL + pp];
        if (j > 0  && x > 0)  acc += S[(size_t)(l-1)*LL + pp - 1];
        if (j < 63 && x < 63) acc += S[(size_t)(l+1)*LL + pp + 1];
        D[(size_t)l*LL + pp] = acc * ninv;
    }
}

// ---------------- fuse #1 (flattened diagonal): bufA -> bufB ------------------
__global__ void k_fuse1() {
    int t = blockIdx.x * blockDim.x + threadIdx.x;
    if (t >= BB*LL*1024) return;
    int b = t >> 22;
    int r = t & 4194303;
    int l = r >> 10;
    int p = (r & 1023) << 2;
    const float* S = g_bufA + (size_t)b*LSQ;
    float* D = g_bufB + (size_t)b*LSQ;
    #pragma unroll
    for (int s = 0; s < 4; s++) {
        int pp = p + s;
        float acc = S[(size_t)l*LL + pp];
        if (l > 0    && pp > 0)    acc += S[(size_t)(l-1)*LL + pp - 1];
        if (l < 4095 && pp < 4095) acc += S[(size_t)(l+1)*LL + pp + 1];
        D[(size_t)l*LL + pp] = acc;
    }
}

// ---------------- permutation (i,j,y,x) -> (x,y,j,i): bufB -> bufA ------------
__global__ void k_perm() {
    __shared__ float tile[32][33];
    int z = blockIdx.z;
    int b = z >> 12;
    int jy = z & 4095;
    int j = jy >> 6, y = jy & 63;
    const float* S = g_bufB + (size_t)b*LSQ;
    float* D = g_bufA + (size_t)b*LSQ;
    int i0 = blockIdx.x * 32, x0 = blockIdx.y * 32;
    #pragma unroll
    for (int k = 0; k < 4; k++) {
        int i = i0 + threadIdx.y + k*8;
        tile[threadIdx.y + k*8][threadIdx.x] =
            S[(size_t)(i*64 + j)*LL + y*64 + x0 + threadIdx.x];
    }
    __syncthreads();
    #pragma unroll
    for (int k = 0; k < 4; k++) {
        int x = x0 + threadIdx.y + k*8;
        D[(size_t)(x*64 + y)*LL + j*64 + i0 + threadIdx.x] =
            tile[threadIdx.x][threadIdx.y + k*8];
    }
}

// ---------------- fuse #2 + mask + softmax over u: bufA -> bufB ---------------
__global__ __launch_bounds__(256) void k_softmax() {
    __shared__ float srow[4096];
    __shared__ float sred[8];
    int v = blockIdx.x & 4095;
    int b = blockIdx.x >> 12;
    const float* S = g_bufA + (size_t)b*LSQ;
    float* D = g_bufB + (size_t)b*LSQ;
    int tid = threadIdx.x;
    int lane = tid & 31, wid = tid >> 5;

    float lmax = -1e30f;
    for (int u = tid; u < 4096; u += 256) {
        float acc = S[(size_t)v*LL + u];
        if (v > 0    && u > 0)    acc += S[(size_t)(v-1)*LL + u - 1];
        if (v < 4095 && u < 4095) acc += S[(size_t)(v+1)*LL + u + 1];
        float val = g_maskP[b*LL + u] ? -1000.f : acc;
        val *= 10.f;
        srow[u] = val;
        lmax = fmaxf(lmax, val);
    }
    #pragma unroll
    for (int o = 16; o; o >>= 1) lmax = fmaxf(lmax, __shfl_xor_sync(0xffffffffu, lmax, o));
    if (lane == 0) sred[wid] = lmax;
    __syncthreads();
    if (tid == 0) {
        float m = sred[0];
        #pragma unroll
        for (int w = 1; w < 8; w++) m = fmaxf(m, sred[w]);
        sred[0] = m;
    }
    __syncthreads();
    float gmax = sred[0];
    __syncthreads();

    float lsum = 0.f;
    for (int u = tid; u < 4096; u += 256) {
        float e = __expf(srow[u] - gmax);
        srow[u] = e;
        lsum += e;
    }
    #pragma unroll
    for (int o = 16; o; o >>= 1) lsum += __shfl_xor_sync(0xffffffffu, lsum, o);
    if (lane == 0) sred[wid] = lsum;
    __syncthreads();
    if (tid == 0) {
        float s2 = 0.f;
        #pragma unroll
        for (int w = 0; w < 8; w++) s2 += sred[w];
        sred[0] = s2;
    }
    __syncthreads();
    float inv = 1.f / sred[0];
    for (int u = tid; u < 4096; u += 256)
        D[(size_t)v*LL + u] = srow[u] * inv;
}

// ---------------- GEMM2: OutCol[pp,e] = sum_u softN[pp,u] * colsP[u,e] --------
__global__ __launch_bounds__(256) void k_gemm2() {
    const int N = 1024, K = 4096;
    int b = blockIdx.z;
    const float* A  = g_bufB  + (size_t)b*LSQ;
    const float* Bm = g_colsP + (size_t)b*LL*EE;
    float*       Cm = g_outcol+ (size_t)b*LL*EE;
    int m0 = blockIdx.y * 128, n0 = blockIdx.x * 128;
    __shared__ float As[8][128];
    __shared__ float Bs[8][128];
    int tid = threadIdx.x;
    int arow = tid >> 1, acol = (tid & 1) * 4;
    int brow = tid >> 5, bcol = (tid & 31) * 4;
    int tr = tid >> 4, tc = tid & 15;
    float acc[8][8];
    #pragma unroll
    for (int r = 0; r < 8; r++)
        #pragma unroll
        for (int s = 0; s < 8; s++) acc[r][s] = 0.f;

    for (int k0 = 0; k0 < K; k0 += 8) {
        float4 av = *(const float4*)(A + (size_t)(m0 + arow)*K + k0 + acol);
        As[acol+0][arow] = av.x; As[acol+1][arow] = av.y;
        As[acol+2][arow] = av.z; As[acol+3][arow] = av.w;
        float4 bv = *(const float4*)(Bm + (size_t)(k0 + brow)*N + n0 + bcol);
        *(float4*)&Bs[brow][bcol] = bv;
        __syncthreads();
        #pragma unroll
        for (int k = 0; k < 8; k++) {
            float4 a0 = *(float4*)&As[k][tr*8];
            float4 a1 = *(float4*)&As[k][tr*8 + 4];
            float4 b0 = *(float4*)&Bs[k][tc*8];
            float4 b1 = *(float4*)&Bs[k][tc*8 + 4];
            float ar[8] = {a0.x,a0.y,a0.z,a0.w,a1.x,a1.y,a1.z,a1.w};
            float br[8] = {b0.x,b0.y,b0.z,b0.w,b1.x,b1.y,b1.z,b1.w};
            #pragma unroll
            for (int r = 0; r < 8; r++)
                #pragma unroll
                for (int s = 0; s < 8; s++) acc[r][s] += ar[r] * br[s];
        }
        __syncthreads();
    }
    #pragma unroll
    for (int r = 0; r < 8; r++) {
        float4 v0 = make_float4(acc[r][0], acc[r][1], acc[r][2], acc[r][3]);
        float4 v1 = make_float4(acc[r][4], acc[r][5], acc[r][6], acc[r][7]);
        float* base = Cm + (size_t)(m0 + tr*8 + r)*N + n0 + tc*8;
        *(float4*)(base)     = v0;
        *(float4*)(base + 4) = v1;
    }
}

// ---------------- overlap-add (transposed conv gather) ------------------------
__global__ void k_overlap(float* __restrict__ out) {
    int idx = blockIdx.x * blockDim.x + threadIdx.x;
    if (idx >= BB*CC*HH*WW) return;
    int X = idx & 127, Y = (idx >> 7) & 127, c = (idx >> 14) & 63, b = idx >> 20;
    float acc = 0.f;
    int y0 = (Y + 1) >> 1;
    int x0 = (X + 1) >> 1;
    #pragma unroll
    for (int dy = 0; dy < 2; dy++) {
        int yc = y0 - dy;
        if (yc < 0 || yc >= 64) continue;
        int ki = Y + 1 - 2*yc;
        if (ki < 0 || ki > 3) continue;
        #pragma unroll
        for (int dx = 0; dx < 2; dx++) {
            int xc = x0 - dx;
            if (xc < 0 || xc >= 64) continue;
            int kj = X + 1 - 2*xc;
            if (kj < 0 || kj > 3) continue;
            acc += g_outcol[((size_t)b*LL + xc*64 + yc)*EE + c*16 + ki*4 + kj];
        }
    }
    out[idx] = acc;
}

// ---------------- launch -------------------------------------------------------
extern "C" void kernel_launch(void* const* d_in, const int* in_sizes, int n_in,
                              void* d_out, int out_size) {
    const float* fg   = (const float*)d_in[0];
    const float* bg   = (const float*)d_in[1];
    const float* mask = (const float*)d_in[2];
    float* out = (float*)d_out;

    k_fgT<<<2048, 256>>>(fg);
    k_bgD<<<2048, 256>>>(bg);
    k_sq<<<1024, 256>>>();
    k_normmask<<<32, 256>>>(mask);
    k_cols<<<32768, 256>>>(bg);

    k_gemm1<<<dim3(64, 64, BB), 256>>>();          // S0 -> bufA
    k_diagA<<<32768, 256>>>();                     // bufA -> bufB
    k_diagB<<<32768, 256>>>();                     // bufB -> bufA (+norm)
    k_fuse1<<<32768, 256>>>();                     // bufA -> bufB
    k_perm<<<dim3(2, 2, BB*4096), dim3(32, 8)>>>();// bufB -> bufA
    k_softmax<<<BB*4096, 256>>>();                 // bufA -> bufB
    k_gemm2<<<dim3(8, 32, BB), 256>>>();           // bufB x colsP -> outcol
    k_overlap<<<8192, 256>>>(out);
}

// round 3
// speedup vs baseline: 1.7995x; 1.7995x over previous
#include <cuda_runtime.h>
#include <cuda_bf16.h>
#include <cstdint>
#include <math.h>

// Problem constants
#define BB 2
#define CC 64
#define HH 128
#define WW 128
#define HS 64          // downsampled H=W
#define LL 4096        // HS*HS
#define EE 1024        // CC*16 (4x4 patch)
#define LSQ (4096*4096)

// ---------------- scratch (device globals; no allocation allowed) -------------
__device__ float g_fgT[BB*CC*LL];          // [b][c][p]
__device__ float g_bgD[BB*LL*CC];          // [b][l][c]
__device__ float g_sq[BB*LL];
__device__ float g_ninv[BB*LL];
__device__ int   g_maskP[BB*LL];           // indexed by permuted a = j*64+i
__device__ __nv_bfloat16 g_colsH[(size_t)BB*LL*EE];  // cols hi, row a = j*64+i
__device__ __nv_bfloat16 g_colsL[(size_t)BB*LL*EE];  // cols lo
__device__ float g_bufA[(size_t)BB*LSQ];     // 134 MB
__device__ float g_bufB[(size_t)BB*LSQ];     // 134 MB
__device__ __nv_bfloat16 g_softH[(size_t)BB*LSQ];    // softmax hi (67 MB)
__device__ __nv_bfloat16 g_softL[(size_t)BB*LSQ];    // softmax lo
__device__ float g_outcol[(size_t)BB*LL*EE]; // row pp = x*64+y

// ---------------- prep kernels -----------------------------------------------
__global__ void k_fgT(const float* __restrict__ fg) {
    int t = blockIdx.x * blockDim.x + threadIdx.x;
    if (t >= BB*CC*LL) return;
    int p = t & 4095, c = (t >> 12) & 63, b = t >> 18;
    int y = p >> 6, x = p & 63;
    g_fgT[((size_t)b*CC + c)*LL + p] =
        fg[(((size_t)b*CC + c)*HH + 2*y)*WW + 2*x];
}

__global__ void k_bgD(const float* __restrict__ bg) {
    int t = blockIdx.x * blockDim.x + threadIdx.x;
    if (t >= BB*LL*CC) return;
    int c = t & 63, l = (t >> 6) & 4095, b = t >> 18;
    int i = l >> 6, j = l & 63;
    g_bgD[((size_t)b*LL + l)*CC + c] =
        bg[(((size_t)b*CC + c)*HH + 2*i)*WW + 2*j];
}

// per-location sum of squares over channels (one warp per l)
__global__ void k_sq() {
    int gid = blockIdx.x * blockDim.x + threadIdx.x;
    int gw = gid >> 5;
    int lane = gid & 31;
    if (gw >= BB*LL) return;
    const float* row = g_bgD + (size_t)gw * CC;
    float v0 = row[lane], v1 = row[lane + 32];
    float s = v0*v0 + v1*v1;
    #pragma unroll
    for (int o = 16; o; o >>= 1) s += __shfl_xor_sync(0xffffffffu, s, o);
    if (lane == 0) g_sq[gw] = s;
}

// patch norms (3x3 window of sq) and mask flags (written permuted)
__global__ void k_normmask(const float* __restrict__ mask) {
    int t = blockIdx.x * blockDim.x + threadIdx.x;
    if (t >= BB*LL) return;
    int b = t >> 12, l = t & 4095;
    int i = l >> 6, j = l & 63;
    float ss = 0.f, ms = 0.f;
    for (int di = -1; di <= 1; di++) {
        int ii = i + di; if (ii < 0 || ii >= HS) continue;
        for (int dj = -1; dj <= 1; dj++) {
            int jj = j + dj; if (jj < 0 || jj >= HS) continue;
            ss += g_sq[b*LL + ii*HS + jj];
            ms += mask[((size_t)b*HH + 2*ii)*WW + 2*jj];
        }
    }
    g_ninv[t] = 1.f / fmaxf(sqrtf(ss), 1e-3f);
    g_maskP[b*LL + j*HS + i] = (ms == 0.f) ? 1 : 0;
}

// 4x4 stride-2 patches of full-res background, rows permuted: a = j*64+i
// Written as bf16 hi/lo split for tensor-core GEMM2.
__global__ void k_cols(const float* __restrict__ bg) {
    int t = blockIdx.x * blockDim.x + threadIdx.x;
    if (t >= BB*LL*EE) return;
    int e = t & 1023;
    int a = (t >> 10) & 4095;
    int b = t >> 22;
    int j = a >> 6, i = a & 63;
    int c = e >> 4, ki = (e >> 2) & 3, kj = e & 3;
    int Y = 2*i - 1 + ki, X = 2*j - 1 + kj;
    float v = 0.f;
    if (Y >= 0 && Y < HH && X >= 0 && X < WW)
        v = bg[(((size_t)b*CC + c)*HH + Y)*WW + X];
    __nv_bfloat16 h = __float2bfloat16(v);
    g_colsH[(size_t)t] = h;
    g_colsL[(size_t)t] = __float2bfloat16(v - __bfloat162float(h));
}

// ---------------- GEMM1: S0[l,p] = sum_c bgD[l,c] * fgT[c,p]  -> bufA ---------
__global__ __launch_bounds__(256) void k_gemm1() {
    __shared__ float As[64][65];   // [l][c]
    __shared__ float Bs[64][65];   // [c][p]
    int b = blockIdx.z;
    int l0 = blockIdx.y * 64, p0 = blockIdx.x * 64;
    int tid = threadIdx.x;
    for (int t = tid; t < 4096; t += 256) {
        int r = t >> 6, c = t & 63;
        As[r][c] = g_bgD[((size_t)b*LL + l0 + r)*CC + c];
        Bs[r][c] = g_fgT[((size_t)b*CC + r)*LL + p0 + c];
    }
    __syncthreads();
    int tr = tid >> 4, tc = tid & 15;
    float acc[4][4];
    #pragma unroll
    for (int r = 0; r < 4; r++) {
        #pragma unroll
        for (int s = 0; s < 4; s++) acc[r][s] = 0.f;
    }
    #pragma unroll 8
    for (int k = 0; k < 64; k++) {
        float ar[4], br[4];
        #pragma unroll
        for (int r = 0; r < 4; r++) ar[r] = As[tr*4 + r][k];
        #pragma unroll
        for (int s = 0; s < 4; s++) br[s] = Bs[k][tc*4 + s];
        #pragma unroll
        for (int r = 0; r < 4; r++) {
            #pragma unroll
            for (int s = 0; s < 4; s++) acc[r][s] += ar[r] * br[s];
        }
    }
    float* D = g_bufA + (size_t)b*LSQ;
    #pragma unroll
    for (int r = 0; r < 4; r++) {
        float4 v = make_float4(acc[r][0], acc[r][1], acc[r][2], acc[r][3]);
        *(float4*)(D + (size_t)(l0 + tr*4 + r)*LL + p0 + tc*4) = v;
    }
}

// ---------------- fused 9-tap patch-sum + norm: bufA -> bufB ------------------
__global__ void k_diag9() {
    int t = blockIdx.x * blockDim.x + threadIdx.x;
    if (t >= BB*LL*1024) return;
    int b = t >> 22;
    int r = t & 4194303;
    int l = r >> 10;
    int p = (r & 1023) << 2;
    const float* S = g_bufA + (size_t)b*LSQ;
    float* D = g_bufB + (size_t)b*LSQ;
    int j = l & 63;
    float ninv = g_ninv[b*LL + l];
    #pragma unroll
    for (int s = 0; s < 4; s++) {
        int pp = p + s;
        int x = pp & 63;
        float acc = 0.f;
        #pragma unroll
        for (int dj = -1; dj <= 1; dj++) {
            if (j + dj < 0 || j + dj > 63 || x + dj < 0 || x + dj > 63) continue;
            #pragma unroll
            for (int di = -1; di <= 1; di++) {
                int l2 = l + dj + 64*di;
                int p2 = pp + dj + 64*di;
                if (l2 >= 0 && l2 < LL && p2 >= 0 && p2 < LL)
                    acc += S[(size_t)l2*LL + p2];
            }
        }
        D[(size_t)l*LL + pp] = acc * ninv;
    }
}

// ---------------- fuse #1 (flattened diagonal): bufB -> bufA ------------------
__global__ void k_fuse1() {
    int t = blockIdx.x * blockDim.x + threadIdx.x;
    if (t >= BB*LL*1024) return;
    int b = t >> 22;
    int r = t & 4194303;
    int l = r >> 10;
    int p = (r & 1023) << 2;
    const float* S = g_bufB + (size_t)b*LSQ;
    float* D = g_bufA + (size_t)b*LSQ;
    #pragma unroll
    for (int s = 0; s < 4; s++) {
        int pp = p + s;
        float acc = S[(size_t)l*LL + pp];
        if (l > 0    && pp > 0)    acc += S[(size_t)(l-1)*LL + pp - 1];
        if (l < 4095 && pp < 4095) acc += S[(size_t)(l+1)*LL + pp + 1];
        D[(size_t)l*LL + pp] = acc;
    }
}

// ---------------- permutation (i,j,y,x) -> (x,y,j,i): bufA -> bufB ------------
__global__ void k_perm() {
    __shared__ float tile[32][33];
    int z = blockIdx.z;
    int b = z >> 12;
    int jy = z & 4095;
    int j = jy >> 6, y = jy & 63;
    const float* S = g_bufA + (size_t)b*LSQ;
    float* D = g_bufB + (size_t)b*LSQ;
    int i0 = blockIdx.x * 32, x0 = blockIdx.y * 32;
    #pragma unroll
    for (int k = 0; k < 4; k++) {
        int i = i0 + threadIdx.y + k*8;
        tile[threadIdx.y + k*8][threadIdx.x] =
            S[(size_t)(i*64 + j)*LL + y*64 + x0 + threadIdx.x];
    }
    __syncthreads();
    #pragma unroll
    for (int k = 0; k < 4; k++) {
        int x = x0 + threadIdx.y + k*8;
        D[(size_t)(x*64 + y)*LL + j*64 + i0 + threadIdx.x] =
            tile[threadIdx.x][threadIdx.y + k*8];
    }
}

// ---------------- fuse #2 + mask + softmax over u: bufB -> softH/softL --------
__global__ __launch_bounds__(256) void k_softmax() {
    __shared__ float srow[4096];
    __shared__ float sred[8];
    int v = blockIdx.x & 4095;
    int b = blockIdx.x >> 12;
    const float* S = g_bufB + (size_t)b*LSQ;
    __nv_bfloat16* DH = g_softH + (size_t)b*LSQ;
    __nv_bfloat16* DL = g_softL + (size_t)b*LSQ;
    int tid = threadIdx.x;
    int lane = tid & 31, wid = tid >> 5;

    float lmax = -1e30f;
    for (int u = tid; u < 4096; u += 256) {
        float acc = S[(size_t)v*LL + u];
        if (v > 0    && u > 0)    acc += S[(size_t)(v-1)*LL + u - 1];
        if (v < 4095 && u < 4095) acc += S[(size_t)(v+1)*LL + u + 1];
        float val = g_maskP[b*LL + u] ? -1000.f : acc;
        val *= 10.f;
        srow[u] = val;
        lmax = fmaxf(lmax, val);
    }
    #pragma unroll
    for (int o = 16; o; o >>= 1) lmax = fmaxf(lmax, __shfl_xor_sync(0xffffffffu, lmax, o));
    if (lane == 0) sred[wid] = lmax;
    __syncthreads();
    if (tid == 0) {
        float m = sred[0];
        #pragma unroll
        for (int w = 1; w < 8; w++) m = fmaxf(m, sred[w]);
        sred[0] = m;
    }
    __syncthreads();
    float gmax = sred[0];
    __syncthreads();

    float lsum = 0.f;
    for (int u = tid; u < 4096; u += 256) {
        float e = __expf(srow[u] - gmax);
        srow[u] = e;
        lsum += e;
    }
    #pragma unroll
    for (int o = 16; o; o >>= 1) lsum += __shfl_xor_sync(0xffffffffu, lsum, o);
    if (lane == 0) sred[wid] = lsum;
    __syncthreads();
    if (tid == 0) {
        float s2 = 0.f;
        #pragma unroll
        for (int w = 0; w < 8; w++) s2 += sred[w];
        sred[0] = s2;
    }
    __syncthreads();
    float inv = 1.f / sred[0];
    for (int u = tid; u < 4096; u += 256) {
        float val = srow[u] * inv;
        __nv_bfloat16 h = __float2bfloat16(val);
        DH[(size_t)v*LL + u] = h;
        DL[(size_t)v*LL + u] = __float2bfloat16(val - __bfloat162float(h));
    }
}

// ---------------- tensor-core GEMM2 helpers -----------------------------------
__device__ __forceinline__ void ldsm_x4(uint32_t* r, uint32_t addr) {
    asm volatile("ldmatrix.sync.aligned.m8n8.x4.shared.b16 {%0,%1,%2,%3}, [%4];"
        : "=r"(r[0]), "=r"(r[1]), "=r"(r[2]), "=r"(r[3]) : "r"(addr));
}
__device__ __forceinline__ void ldsm_x4_t(uint32_t* r, uint32_t addr) {
    asm volatile("ldmatrix.sync.aligned.m8n8.x4.trans.shared.b16 {%0,%1,%2,%3}, [%4];"
        : "=r"(r[0]), "=r"(r[1]), "=r"(r[2]), "=r"(r[3]) : "r"(addr));
}
__device__ __forceinline__ void mma_bf16(float* c, const uint32_t* a, const uint32_t* b) {
    asm volatile(
        "mma.sync.aligned.m16n8k16.row.col.f32.bf16.bf16.f32 "
        "{%0,%1,%2,%3}, {%4,%5,%6,%7}, {%8,%9}, {%0,%1,%2,%3};"
        : "+f"(c[0]), "+f"(c[1]), "+f"(c[2]), "+f"(c[3])
        : "r"(a[0]), "r"(a[1]), "r"(a[2]), "r"(a[3]), "r"(b[0]), "r"(b[1]));
}

// ---------------- GEMM2: OutCol[pp,e] = sum_u soft[pp,u] * cols[u,e] ----------
// bf16 x3 split on tensor cores. CTA tile 128(M)x128(N), 8 warps (2x4),
// warp tile 64x32, k-step 32.
__global__ __launch_bounds__(256) void k_gemm2() {
    __shared__ __nv_bfloat16 sAh[128][40];  // 80B row stride (16B multiple)
    __shared__ __nv_bfloat16 sAl[128][40];
    __shared__ __nv_bfloat16 sBh[32][136];  // 272B row stride (16B multiple)
    __shared__ __nv_bfloat16 sBl[32][136];

    int b = blockIdx.z;
    const __nv_bfloat16* Ah = g_softH + (size_t)b*LSQ;
    const __nv_bfloat16* Al = g_softL + (size_t)b*LSQ;
    const __nv_bfloat16* Bh = g_colsH + (size_t)b*LL*EE;
    const __nv_bfloat16* Bl = g_colsL + (size_t)b*LL*EE;
    float* Cm = g_outcol + (size_t)b*LL*EE;

    int m0 = blockIdx.y * 128, n0 = blockIdx.x * 128;
    int tid = threadIdx.x;
    int lane = tid & 31, warp = tid >> 5;
    int wm = warp & 1, wn = warp >> 1;      // warp tile: rows wm*64, cols wn*32

    uint32_t bAh = (uint32_t)__cvta_generic_to_shared(&sAh[0][0]);
    uint32_t bAl = (uint32_t)__cvta_generic_to_shared(&sAl[0][0]);
    uint32_t bBh = (uint32_t)__cvta_generic_to_shared(&sBh[0][0]);
    uint32_t bBl = (uint32_t)__cvta_generic_to_shared(&sBl[0][0]);

    float acc[4][4][4];
    #pragma unroll
    for (int mt = 0; mt < 4; mt++) {
        #pragma unroll
        for (int nt = 0; nt < 4; nt++) {
            #pragma unroll
            for (int q = 0; q < 4; q++) acc[mt][nt][q] = 0.f;
        }
    }

    int lr = lane & 15, lc = lane >> 4;

    for (int k0 = 0; k0 < LL; k0 += 32) {
        __syncthreads();
        #pragma unroll
        for (int i = 0; i < 2; i++) {
            int cid = tid*2 + i;                       // 0..511
            int m = cid >> 2, kc = (cid & 3) * 8;
            *(uint4*)&sAh[m][kc] = *(const uint4*)(Ah + (size_t)(m0+m)*LL + k0 + kc);
            *(uint4*)&sAl[m][kc] = *(const uint4*)(Al + (size_t)(m0+m)*LL + k0 + kc);
            int kb = cid >> 4, nc = (cid & 15) * 8;
            *(uint4*)&sBh[kb][nc] = *(const uint4*)(Bh + (size_t)(k0+kb)*EE + n0 + nc);
            *(uint4*)&sBl[kb][nc] = *(const uint4*)(Bl + (size_t)(k0+kb)*EE + n0 + nc);
        }
        __syncthreads();

        #pragma unroll
        for (int kk = 0; kk < 32; kk += 16) {
            uint32_t ah[4][4], al[4][4], bh[4][2], bl[4][2];
            #pragma unroll
            for (int mt = 0; mt < 4; mt++) {
                uint32_t offa = (uint32_t)((wm*64 + mt*16 + lr) * 40 + kk + lc*8) * 2u;
                ldsm_x4(ah[mt], bAh + offa);
                ldsm_x4(al[mt], bAl + offa);
            }
            #pragma unroll
            for (int ntp = 0; ntp < 2; ntp++) {
                uint32_t offb = (uint32_t)((kk + lr) * 136 + wn*32 + ntp*16 + lc*8) * 2u;
                uint32_t rh[4], rl[4];
                ldsm_x4_t(rh, bBh + offb);
                ldsm_x4_t(rl, bBl + offb);
                bh[ntp*2][0] = rh[0]; bh[ntp*2][1] = rh[1];
                bh[ntp*2+1][0] = rh[2]; bh[ntp*2+1][1] = rh[3];
                bl[ntp*2][0] = rl[0]; bl[ntp*2][1] = rl[1];
                bl[ntp*2+1][0] = rl[2]; bl[ntp*2+1][1] = rl[3];
            }
            #pragma unroll
            for (int mt = 0; mt < 4; mt++) {
                #pragma unroll
                for (int nt = 0; nt < 4; nt++) {
                    mma_bf16(acc[mt][nt], ah[mt], bh[nt]);
                    mma_bf16(acc[mt][nt], ah[mt], bl[nt]);
                    mma_bf16(acc[mt][nt], al[mt], bh[nt]);
                }
            }
        }
    }

    // epilogue: c0,c1 -> (row g, cols tig*2,+1); c2,c3 -> row g+8
    int g = lane >> 2, tig = lane & 3;
    #pragma unroll
    for (int mt = 0; mt < 4; mt++) {
        int row0 = m0 + wm*64 + mt*16 + g;
        #pragma unroll
        for (int nt = 0; nt < 4; nt++) {
            int col = n0 + wn*32 + nt*8 + tig*2;
            float2 v0 = make_float2(acc[mt][nt][0], acc[mt][nt][1]);
            float2 v1 = make_float2(acc[mt][nt][2], acc[mt][nt][3]);
            *(float2*)(Cm + (size_t)row0*EE + col)       = v0;
            *(float2*)(Cm + (size_t)(row0+8)*EE + col)   = v1;
        }
    }
}

// ---------------- overlap-add (transposed conv gather) ------------------------
__global__ void k_overlap(float* __restrict__ out) {
    int idx = blockIdx.x * blockDim.x + threadIdx.x;
    if (idx >= BB*CC*HH*WW) return;
    int X = idx & 127, Y = (idx >> 7) & 127, c = (idx >> 14) & 63, b = idx >> 20;
    float acc = 0.f;
    int y0 = (Y + 1) >> 1;
    int x0 = (X + 1) >> 1;
    #pragma unroll
    for (int dy = 0; dy < 2; dy++) {
        int yc = y0 - dy;
        if (yc < 0 || yc >= 64) continue;
        int ki = Y + 1 - 2*yc;
        if (ki < 0 || ki > 3) continue;
        #pragma unroll
        for (int dx = 0; dx < 2; dx++) {
            int xc = x0 - dx;
            if (xc < 0 || xc >= 64) continue;
            int kj = X + 1 - 2*xc;
            if (kj < 0 || kj > 3) continue;
            acc += g_outcol[((size_t)b*LL + xc*64 + yc)*EE + c*16 + ki*4 + kj];
        }
    }
    out[idx] = acc;
}

// ---------------- launch -------------------------------------------------------
extern "C" void kernel_launch(void* const* d_in, const int* in_sizes, int n_in,
                              void* d_out, int out_size) {
    const float* fg   = (const float*)d_in[0];
    const float* bg   = (const float*)d_in[1];
    const float* mask = (const float*)d_in[2];
    float* out = (float*)d_out;

    k_fgT<<<2048, 256>>>(fg);
    k_bgD<<<2048, 256>>>(bg);
    k_sq<<<1024, 256>>>();
    k_normmask<<<32, 256>>>(mask);
    k_cols<<<32768, 256>>>(bg);

    k_gemm1<<<dim3(64, 64, BB), 256>>>();            // S0 -> bufA
    k_diag9<<<32768, 256>>>();                       // bufA -> bufB (fused + norm)
    k_fuse1<<<32768, 256>>>();                       // bufB -> bufA
    k_perm<<<dim3(2, 2, BB*4096), dim3(32, 8)>>>();  // bufA -> bufB
    k_softmax<<<BB*4096, 256>>>();                   // bufB -> softH/softL (bf16)
    k_gemm2<<<dim3(8, 32, BB), 256>>>();             // tensor cores -> outcol
    k_overlap<<<8192, 256>>>(out);
}

// round 5
// speedup vs baseline: 2.1930x; 1.2187x over previous
#include <cuda_runtime.h>
#include <cuda_bf16.h>
#include <cuda_fp16.h>
#include <cstdint>
#include <math.h>

// Problem constants
#define BB 2
#define CC 64
#define HH 128
#define WW 128
#define HS 64          // downsampled H=W
#define LL 4096        // HS*HS
#define EE 1024        // CC*16 (4x4 patch)
#define LSQ (4096*4096)

// ---------------- scratch (device globals; no allocation allowed) -------------
__device__ float  g_bgD[BB*LL*CC];          // [b][l][c] fp32 (for norms)
__device__ __half g_bgDH[BB*LL*CC];         // fp16 hi
__device__ __half g_bgDL[BB*LL*CC];         // fp16 lo
__device__ __half g_fgTH[BB*CC*LL];         // [b][c][p] fp16 hi
__device__ __half g_fgTL[BB*CC*LL];         // fp16 lo
__device__ float  g_sq[BB*LL];
__device__ float  g_ninv[BB*LL];
__device__ int    g_maskP[BB*LL];           // indexed by permuted a = j*64+i
__device__ __half g_colsF[(size_t)BB*LL*EE];  // cols fp16, row a = j*64+i
__device__ float  g_bufA[(size_t)BB*LSQ];     // 134 MB
__device__ float  g_bufB[(size_t)BB*LSQ];     // 134 MB
__device__ __half g_softH[(size_t)BB*LSQ];    // softmax fp16 hi
__device__ __half g_softL[(size_t)BB*LSQ];    // softmax fp16 lo
__device__ float  g_outcol[(size_t)BB*LL*EE]; // row pp = x*64+y

// ---------------- prep kernels -----------------------------------------------
__global__ void k_fgT(const float* __restrict__ fg) {
    int t = blockIdx.x * blockDim.x + threadIdx.x;
    if (t >= BB*CC*LL) return;
    int p = t & 4095, c = (t >> 12) & 63, b = t >> 18;
    int y = p >> 6, x = p & 63;
    float v = fg[(((size_t)b*CC + c)*HH + 2*y)*WW + 2*x];
    __half h = __float2half(v);
    size_t o = ((size_t)b*CC + c)*LL + p;
    g_fgTH[o] = h;
    g_fgTL[o] = __float2half(v - __half2float(h));
}

__global__ void k_bgD(const float* __restrict__ bg) {
    int t = blockIdx.x * blockDim.x + threadIdx.x;
    if (t >= BB*LL*CC) return;
    int c = t & 63, l = (t >> 6) & 4095, b = t >> 18;
    int i = l >> 6, j = l & 63;
    float v = bg[(((size_t)b*CC + c)*HH + 2*i)*WW + 2*j];
    size_t o = ((size_t)b*LL + l)*CC + c;
    g_bgD[o] = v;
    __half h = __float2half(v);
    g_bgDH[o] = h;
    g_bgDL[o] = __float2half(v - __half2float(h));
}

// per-location sum of squares over channels (one warp per l)
__global__ void k_sq() {
    int gid = blockIdx.x * blockDim.x + threadIdx.x;
    int gw = gid >> 5;
    int lane = gid & 31;
    if (gw >= BB*LL) return;
    const float* row = g_bgD + (size_t)gw * CC;
    float v0 = row[lane], v1 = row[lane + 32];
    float s = v0*v0 + v1*v1;
    #pragma unroll
    for (int o = 16; o; o >>= 1) s += __shfl_xor_sync(0xffffffffu, s, o);
    if (lane == 0) g_sq[gw] = s;
}

// patch norms (3x3 window of sq) and mask flags (written permuted)
__global__ void k_normmask(const float* __restrict__ mask) {
    int t = blockIdx.x * blockDim.x + threadIdx.x;
    if (t >= BB*LL) return;
    int b = t >> 12, l = t & 4095;
    int i = l >> 6, j = l & 63;
    float ss = 0.f, ms = 0.f;
    for (int di = -1; di <= 1; di++) {
        int ii = i + di; if (ii < 0 || ii >= HS) continue;
        for (int dj = -1; dj <= 1; dj++) {
            int jj = j + dj; if (jj < 0 || jj >= HS) continue;
            ss += g_sq[b*LL + ii*HS + jj];
            ms += mask[((size_t)b*HH + 2*ii)*WW + 2*jj];
        }
    }
    g_ninv[t] = 1.f / fmaxf(sqrtf(ss), 1e-3f);
    g_maskP[b*LL + j*HS + i] = (ms == 0.f) ? 1 : 0;
}

// 4x4 stride-2 patches of full-res background, rows permuted: a = j*64+i
__global__ void k_cols(const float* __restrict__ bg) {
    int t = blockIdx.x * blockDim.x + threadIdx.x;
    if (t >= BB*LL*EE) return;
    int e = t & 1023;
    int a = (t >> 10) & 4095;
    int b = t >> 22;
    int j = a >> 6, i = a & 63;
    int c = e >> 4, ki = (e >> 2) & 3, kj = e & 3;
    int Y = 2*i - 1 + ki, X = 2*j - 1 + kj;
    float v = 0.f;
    if (Y >= 0 && Y < HH && X >= 0 && X < WW)
        v = bg[(((size_t)b*CC + c)*HH + Y)*WW + X];
    g_colsF[(size_t)t] = __float2half(v);
}

// ---------------- tensor-core helpers -----------------------------------------
__device__ __forceinline__ void ldsm_x4(uint32_t* r, uint32_t addr) {
    asm volatile("ldmatrix.sync.aligned.m8n8.x4.shared.b16 {%0,%1,%2,%3}, [%4];"
        : "=r"(r[0]), "=r"(r[1]), "=r"(r[2]), "=r"(r[3]) : "r"(addr));
}
__device__ __forceinline__ void ldsm_x4_t(uint32_t* r, uint32_t addr) {
    asm volatile("ldmatrix.sync.aligned.m8n8.x4.trans.shared.b16 {%0,%1,%2,%3}, [%4];"
        : "=r"(r[0]), "=r"(r[1]), "=r"(r[2]), "=r"(r[3]) : "r"(addr));
}
__device__ __forceinline__ void mma_f16(float* c, const uint32_t* a, const uint32_t* b) {
    asm volatile(
        "mma.sync.aligned.m16n8k16.row.col.f32.f16.f16.f32 "
        "{%0,%1,%2,%3}, {%4,%5,%6,%7}, {%8,%9}, {%0,%1,%2,%3};"
        : "+f"(c[0]), "+f"(c[1]), "+f"(c[2]), "+f"(c[3])
        : "r"(a[0]), "r"(a[1]), "r"(a[2]), "r"(a[3]), "r"(b[0]), "r"(b[1]));
}
__device__ __forceinline__ void cpa16(uint32_t s, const void* g) {
    asm volatile("cp.async.cg.shared.global [%0], [%1], 16;" :: "r"(s), "l"(g));
}

// ---------------- GEMM1 (tensor): S0[l,p] = sum_c bgD[l,c]*fgT[c,p] -> bufA ---
// fp16 hi/lo both operands, 3 MMAs (ah*bh + ah*bl + al*bh). K=64 in 2 k32 steps.
__global__ __launch_bounds__(256) void k_gemm1() {
    __shared__ __half sAh[128][40], sAl[128][40];
    __shared__ __half sBh[32][136], sBl[32][136];
    int b = blockIdx.z;
    const __half* AH = g_bgDH + (size_t)b*LL*CC;
    const __half* AL = g_bgDL + (size_t)b*LL*CC;
    const __half* BH = g_fgTH + (size_t)b*CC*LL;
    const __half* BL = g_fgTL + (size_t)b*CC*LL;
    float* Cm = g_bufA + (size_t)b*LSQ;

    int m0 = blockIdx.y * 128, n0 = blockIdx.x * 128;
    int tid = threadIdx.x;
    int lane = tid & 31, warp = tid >> 5;
    int wm = warp & 1, wn = warp >> 1;
    int lr = lane & 15, lc = lane >> 4;

    float acc[4][4][4];
    #pragma unroll
    for (int mt = 0; mt < 4; mt++) {
        #pragma unroll
        for (int nt = 0; nt < 4; nt++) {
            #pragma unroll
            for (int q = 0; q < 4; q++) acc[mt][nt][q] = 0.f;
        }
    }

    uint32_t bAh = (uint32_t)__cvta_generic_to_shared(&sAh[0][0]);
    uint32_t bAl = (uint32_t)__cvta_generic_to_shared(&sAl[0][0]);
    uint32_t bBh = (uint32_t)__cvta_generic_to_shared(&sBh[0][0]);
    uint32_t bBl = (uint32_t)__cvta_generic_to_shared(&sBl[0][0]);

    for (int k0 = 0; k0 < 64; k0 += 32) {
        __syncthreads();
        #pragma unroll
        for (int i = 0; i < 2; i++) {
            int cid = tid + i*256;                    // 0..511
            int m = cid >> 2, kc = (cid & 3) * 8;
            *(uint4*)&sAh[m][kc] = *(const uint4*)(AH + (size_t)(m0+m)*CC + k0 + kc);
            *(uint4*)&sAl[m][kc] = *(const uint4*)(AL + (size_t)(m0+m)*CC + k0 + kc);
            int kb = cid >> 4, nc = (cid & 15) * 8;
            *(uint4*)&sBh[kb][nc] = *(const uint4*)(BH + (size_t)(k0+kb)*LL + n0 + nc);
            *(uint4*)&sBl[kb][nc] = *(const uint4*)(BL + (size_t)(k0+kb)*LL + n0 + nc);
        }
        __syncthreads();

        #pragma unroll
        for (int kk = 0; kk < 32; kk += 16) {
            uint32_t ah[4][4], al[4][4], bh[4][2], bl[4][2];
            #pragma unroll
            for (int mt = 0; mt < 4; mt++) {
                uint32_t offa = (uint32_t)((wm*64 + mt*16 + lr) * 40 + kk + lc*8) * 2u;
                ldsm_x4(ah[mt], bAh + offa);
                ldsm_x4(al[mt], bAl + offa);
            }
            #pragma unroll
            for (int ntp = 0; ntp < 2; ntp++) {
                uint32_t offb = (uint32_t)((kk + lr) * 136 + wn*32 + ntp*16 + lc*8) * 2u;
                uint32_t rh[4], rl[4];
                ldsm_x4_t(rh, bBh + offb);
                ldsm_x4_t(rl, bBl + offb);
                bh[ntp*2][0] = rh[0]; bh[ntp*2][1] = rh[1];
                bh[ntp*2+1][0] = rh[2]; bh[ntp*2+1][1] = rh[3];
                bl[ntp*2][0] = rl[0]; bl[ntp*2][1] = rl[1];
                bl[ntp*2+1][0] = rl[2]; bl[ntp*2+1][1] = rl[3];
            }
            #pragma unroll
            for (int mt = 0; mt < 4; mt++) {
                #pragma unroll
                for (int nt = 0; nt < 4; nt++) {
                    mma_f16(acc[mt][nt], ah[mt], bh[nt]);
                    mma_f16(acc[mt][nt], ah[mt], bl[nt]);
                    mma_f16(acc[mt][nt], al[mt], bh[nt]);
                }
            }
        }
    }

    int g = lane >> 2, tig = lane & 3;
    #pragma unroll
    for (int mt = 0; mt < 4; mt++) {
        int row0 = m0 + wm*64 + mt*16 + g;
        #pragma unroll
        for (int nt = 0; nt < 4; nt++) {
            int col = n0 + wn*32 + nt*8 + tig*2;
            *(float2*)(Cm + (size_t)row0*LL + col)     = make_float2(acc[mt][nt][0], acc[mt][nt][1]);
            *(float2*)(Cm + (size_t)(row0+8)*LL + col) = make_float2(acc[mt][nt][2], acc[mt][nt][3]);
        }
    }
}

// ---------------- fused 27-tap (diag9 o norm o fuse1): bufA -> bufB -----------
__global__ void k_diagf() {
    int t = blockIdx.x * blockDim.x + threadIdx.x;
    if (t >= BB*LL*1024) return;
    int b = t >> 22;
    int r = t & 4194303;
    int l = r >> 10;
    int p = (r & 1023) << 2;
    const float* S = g_bufA + (size_t)b*LSQ;
    float* D = g_bufB + (size_t)b*LSQ;
    #pragma unroll
    for (int s = 0; s < 4; s++) {
        int pp = p + s;
        float acc = 0.f;
        #pragma unroll
        for (int d = -1; d <= 1; d++) {
            int lcn = l + d, pcn = pp + d;
            if (lcn < 0 || lcn >= LL || pcn < 0 || pcn >= LL) continue;
            int jc = lcn & 63, xc = pcn & 63;
            float inner = 0.f;
            #pragma unroll
            for (int dj = -1; dj <= 1; dj++) {
                if (jc + dj < 0 || jc + dj > 63 || xc + dj < 0 || xc + dj > 63) continue;
                #pragma unroll
                for (int di = -1; di <= 1; di++) {
                    int l2 = lcn + dj + 64*di;
                    int p2 = pcn + dj + 64*di;
                    if (l2 >= 0 && l2 < LL && p2 >= 0 && p2 < LL)
                        inner += S[(size_t)l2*LL + p2];
                }
            }
            acc += inner * g_ninv[b*LL + lcn];
        }
        D[(size_t)l*LL + pp] = acc;
    }
}

// ---------------- permutation (i,j,y,x) -> (x,y,j,i): bufB -> bufA ------------
__global__ void k_perm() {
    __shared__ float tile[32][33];
    int z = blockIdx.z;
    int b = z >> 12;
    int jy = z & 4095;
    int j = jy >> 6, y = jy & 63;
    const float* S = g_bufB + (size_t)b*LSQ;
    float* D = g_bufA + (size_t)b*LSQ;
    int i0 = blockIdx.x * 32, x0 = blockIdx.y * 32;
    #pragma unroll
    for (int k = 0; k < 4; k++) {
        int i = i0 + threadIdx.y + k*8;
        tile[threadIdx.y + k*8][threadIdx.x] =
            S[(size_t)(i*64 + j)*LL + y*64 + x0 + threadIdx.x];
    }
    __syncthreads();
    #pragma unroll
    for (int k = 0; k < 4; k++) {
        int x = x0 + threadIdx.y + k*8;
        D[(size_t)(x*64 + y)*LL + j*64 + i0 + threadIdx.x] =
            tile[threadIdx.x][threadIdx.y + k*8];
    }
}

// ---------------- fuse #2 + mask + softmax over u: bufA -> softH/softL --------
__global__ __launch_bounds__(256) void k_softmax() {
    __shared__ float srow[4096];
    __shared__ float sred[8];
    int v = blockIdx.x & 4095;
    int b = blockIdx.x >> 12;
    const float* S = g_bufA + (size_t)b*LSQ;
    __half* DH = g_softH + (size_t)b*LSQ;
    __half* DL = g_softL + (size_t)b*LSQ;
    int tid = threadIdx.x;
    int lane = tid & 31, wid = tid >> 5;

    float lmax = -1e30f;
    for (int u = tid; u < 4096; u += 256) {
        float acc = S[(size_t)v*LL + u];
        if (v > 0    && u > 0)    acc += S[(size_t)(v-1)*LL + u - 1];
        if (v < 4095 && u < 4095) acc += S[(size_t)(v+1)*LL + u + 1];
        float val = g_maskP[b*LL + u] ? -1000.f : acc;
        val *= 10.f;
        srow[u] = val;
        lmax = fmaxf(lmax, val);
    }
    #pragma unroll
    for (int o = 16; o; o >>= 1) lmax = fmaxf(lmax, __shfl_xor_sync(0xffffffffu, lmax, o));
    if (lane == 0) sred[wid] = lmax;
    __syncthreads();
    if (tid == 0) {
        float m = sred[0];
        #pragma unroll
        for (int w = 1; w < 8; w++) m = fmaxf(m, sred[w]);
        sred[0] = m;
    }
    __syncthreads();
    float gmax = sred[0];
    __syncthreads();

    float lsum = 0.f;
    for (int u = tid; u < 4096; u += 256) {
        float e = __expf(srow[u] - gmax);
        srow[u] = e;
        lsum += e;
    }
    #pragma unroll
    for (int o = 16; o; o >>= 1) lsum += __shfl_xor_sync(0xffffffffu, lsum, o);
    if (lane == 0) sred[wid] = lsum;
    __syncthreads();
    if (tid == 0) {
        float s2 = 0.f;
        #pragma unroll
        for (int w = 0; w < 8; w++) s2 += sred[w];
        sred[0] = s2;
    }
    __syncthreads();
    float inv = 1.f / sred[0];
    for (int u = tid; u < 4096; u += 256) {
        float val = srow[u] * inv;
        __half h = __float2half(val);
        DH[(size_t)v*LL + u] = h;
        DL[(size_t)v*LL + u] = __float2half(val - __half2float(h));
    }
}

// ---------------- GEMM2 (pipelined, static 48KB smem): OutCol = soft @ cols ---
// A = fp16 hi/lo (exact split of softmax), B = single fp16. 2 MMAs per k16.
// CTA tile 128x128, k-step 32, 2-stage cp.async double buffer.
// XOR-swizzled tiles (no padding):
//   A: 128 rows x 64B; 16B chunk c at row m stored at c ^ ((m>>1)&3)
//   B: 32 rows x 256B; 16B chunk c at row k stored at c ^ (k&7)
#define G2_STG 24576u   // per-stage bytes: Ah 8192 + Al 8192 + B 8192
__global__ __launch_bounds__(256) void k_gemm2() {
    __shared__ char smem[2*G2_STG];   // 49152 B
    uint32_t sb = (uint32_t)__cvta_generic_to_shared(smem);

    int b = blockIdx.z;
    const __half* Ah = g_softH + (size_t)b*LSQ;
    const __half* Al = g_softL + (size_t)b*LSQ;
    const __half* Bf = g_colsF + (size_t)b*LL*EE;
    float* Cm = g_outcol + (size_t)b*LL*EE;

    int m0 = blockIdx.y * 128, n0 = blockIdx.x * 128;
    int tid = threadIdx.x;
    int lane = tid & 31, warp = tid >> 5;
    int wm = warp & 1, wn = warp >> 1;
    int lr = lane & 15, lc = lane >> 4;

    float acc[4][4][4];
    #pragma unroll
    for (int mt = 0; mt < 4; mt++) {
        #pragma unroll
        for (int nt = 0; nt < 4; nt++) {
            #pragma unroll
            for (int q = 0; q < 4; q++) acc[mt][nt][q] = 0.f;
        }
    }

    // per-thread load slots (2 chunks per matrix per thread, 512 chunks total)
    int c0 = tid, c1 = tid + 256;
    // A chunk -> (row m, 16B chunk cc), swizzled dst
    int mA0 = c0 >> 2, cA0 = c0 & 3;
    int mA1 = c1 >> 2, cA1 = c1 & 3;
    uint32_t dA0 = (uint32_t)(mA0*64 + (cA0 ^ ((mA0>>1)&3))*16);
    uint32_t dA1 = (uint32_t)(mA1*64 + (cA1 ^ ((mA1>>1)&3))*16);
    // B chunk -> (k-row kb, chunk cc), swizzled dst
    int kB0 = c0 >> 4, cB0 = c0 & 15;
    int kB1 = c1 >> 4, cB1 = c1 & 15;
    uint32_t dB0 = (uint32_t)(kB0*256 + (cB0 ^ (kB0&7))*16);
    uint32_t dB1 = (uint32_t)(kB1*256 + (cB1 ^ (kB1&7))*16);

    const int STEPS = LL / 32;

    // issue stage 0
    {
        uint32_t s0 = sb;
        cpa16(s0 + dA0,          Ah + (size_t)(m0+mA0)*LL + cA0*8);
        cpa16(s0 + dA1,          Ah + (size_t)(m0+mA1)*LL + cA1*8);
        cpa16(s0 + 8192u + dA0,  Al + (size_t)(m0+mA0)*LL + cA0*8);
        cpa16(s0 + 8192u + dA1,  Al + (size_t)(m0+mA1)*LL + cA1*8);
        cpa16(s0 + 16384u + dB0, Bf + (size_t)kB0*EE + n0 + cB0*8);
        cpa16(s0 + 16384u + dB1, Bf + (size_t)kB1*EE + n0 + cB1*8);
        asm volatile("cp.async.commit_group;");
    }

    for (int i = 0; i < STEPS; i++) {
        if (i + 1 < STEPS) {
            int k0 = (i + 1) * 32;
            uint32_t s1 = sb + (uint32_t)(((i + 1) & 1) * G2_STG);
            cpa16(s1 + dA0,          Ah + (size_t)(m0+mA0)*LL + k0 + cA0*8);
            cpa16(s1 + dA1,          Ah + (size_t)(m0+mA1)*LL + k0 + cA1*8);
            cpa16(s1 + 8192u + dA0,  Al + (size_t)(m0+mA0)*LL + k0 + cA0*8);
            cpa16(s1 + 8192u + dA1,  Al + (size_t)(m0+mA1)*LL + k0 + cA1*8);
            cpa16(s1 + 16384u + dB0, Bf + (size_t)(k0+kB0)*EE + n0 + cB0*8);
            cpa16(s1 + 16384u + dB1, Bf + (size_t)(k0+kB1)*EE + n0 + cB1*8);
            asm volatile("cp.async.commit_group;");
            asm volatile("cp.async.wait_group 1;");
        } else {
            asm volatile("cp.async.wait_group 0;");
        }
        __syncthreads();

        uint32_t st = sb + (uint32_t)((i & 1) * G2_STG);
        #pragma unroll
        for (int kk = 0; kk < 32; kk += 16) {
            uint32_t ahf[4][4], alf[4][4], bfr[4][2];
            #pragma unroll
            for (int mt = 0; mt < 4; mt++) {
                int row = wm*64 + mt*16 + lr;
                int ca = (kk >> 3) + lc;                // logical 16B chunk (k)
                uint32_t offa = (uint32_t)(row*64 + ((ca ^ ((row>>1)&3)))*16);
                ldsm_x4(ahf[mt], st + offa);
                ldsm_x4(alf[mt], st + 8192u + offa);
            }
            #pragma unroll
            for (int ntp = 0; ntp < 2; ntp++) {
                int krow = kk + lr;
                int cb = wn*4 + ntp*2 + lc;             // logical 16B chunk (n)
                uint32_t offb = 16384u + (uint32_t)(krow*256 + ((cb ^ (krow&7)))*16);
                uint32_t rh[4];
                ldsm_x4_t(rh, st + offb);
                bfr[ntp*2][0] = rh[0]; bfr[ntp*2][1] = rh[1];
                bfr[ntp*2+1][0] = rh[2]; bfr[ntp*2+1][1] = rh[3];
            }
            #pragma unroll
            for (int mt = 0; mt < 4; mt++) {
                #pragma unroll
                for (int nt = 0; nt < 4; nt++) {
                    mma_f16(acc[mt][nt], ahf[mt], bfr[nt]);
                    mma_f16(acc[mt][nt], alf[mt], bfr[nt]);
                }
            }
        }
        __syncthreads();
    }

    int g = lane >> 2, tig = lane & 3;
    #pragma unroll
    for (int mt = 0; mt < 4; mt++) {
        int row0 = m0 + wm*64 + mt*16 + g;
        #pragma unroll
        for (int nt = 0; nt < 4; nt++) {
            int col = n0 + wn*32 + nt*8 + tig*2;
            *(float2*)(Cm + (size_t)row0*EE + col)     = make_float2(acc[mt][nt][0], acc[mt][nt][1]);
            *(float2*)(Cm + (size_t)(row0+8)*EE + col) = make_float2(acc[mt][nt][2], acc[mt][nt][3]);
        }
    }
}

// ---------------- overlap-add (transposed conv gather) ------------------------
__global__ void k_overlap(float* __restrict__ out) {
    int idx = blockIdx.x * blockDim.x + threadIdx.x;
    if (idx >= BB*CC*HH*WW) return;
    int X = idx & 127, Y = (idx >> 7) & 127, c = (idx >> 14) & 63, b = idx >> 20;
    float acc = 0.f;
    int y0 = (Y + 1) >> 1;
    int x0 = (X + 1) >> 1;
    #pragma unroll
    for (int dy = 0; dy < 2; dy++) {
        int yc = y0 - dy;
        if (yc < 0 || yc >= 64) continue;
        int ki = Y + 1 - 2*yc;
        if (ki < 0 || ki > 3) continue;
        #pragma unroll
        for (int dx = 0; dx < 2; dx++) {
            int xc = x0 - dx;
            if (xc < 0 || xc >= 64) continue;
            int kj = X + 1 - 2*xc;
            if (kj < 0 || kj > 3) continue;
            acc += g_outcol[((size_t)b*LL + xc*64 + yc)*EE + c*16 + ki*4 + kj];
        }
    }
    out[idx] = acc;
}

// ---------------- launch -------------------------------------------------------
extern "C" void kernel_launch(void* const* d_in, const int* in_sizes, int n_in,
                              void* d_out, int out_size) {
    const float* fg   = (const float*)d_in[0];
    const float* bg   = (const float*)d_in[1];
    const float* mask = (const float*)d_in[2];
    float* out = (float*)d_out;

    k_fgT<<<2048, 256>>>(fg);
    k_bgD<<<2048, 256>>>(bg);
    k_sq<<<1024, 256>>>();
    k_normmask<<<32, 256>>>(mask);
    k_cols<<<32768, 256>>>(bg);

    k_gemm1<<<dim3(32, 32, BB), 256>>>();                 // tensor -> bufA
    k_diagf<<<32768, 256>>>();                            // bufA -> bufB (27-tap)
    k_perm<<<dim3(2, 2, BB*4096), dim3(32, 8)>>>();       // bufB -> bufA
    k_softmax<<<BB*4096, 256>>>();                        // bufA -> softH/softL
    k_gemm2<<<dim3(8, 32, BB), 256>>>();                  // pipelined -> outcol
    k_overlap<<<8192, 256>>>(out);
}